// round 5
// baseline (speedup 1.0000x reference)
#include <cuda_runtime.h>
#include <cuda_bf16.h>
#include <cstdint>
#include <math.h>

#define NB 16384
#define ND 256
#define NCTA 296            // persistent CTAs: 2 per SM on 148 SMs

static __device__ __nv_bfloat16 g_qh[NB * ND];  // normalized Q * log2(e)/T, bf16
static __device__ __nv_bfloat16 g_dh[NB * ND];  // normalized D, bf16
static __device__ float g_rowsum[NB];
static __device__ float g_colsum[NB];

__device__ __forceinline__ uint32_t smem_u32(const void* p) {
    uint32_t a;
    asm("{ .reg .u64 t; cvta.to.shared.u64 t, %1; cvt.u32.u64 %0, t; }" : "=r"(a) : "l"(p));
    return a;
}
__device__ __forceinline__ float ex2_approx(float x) {
    float r; asm("ex2.approx.f32 %0, %1;" : "=f"(r) : "f"(x)); return r;
}

// ---------------- setup kernels ----------------
__global__ void zero_kernel(float* out) {
    int i = blockIdx.x * blockDim.x + threadIdx.x;
    if (i < NB) { g_rowsum[i] = 0.0f; g_colsum[i] = 0.0f; }
    if (i == 0) out[0] = 0.0f;
}

// one warp per row: L2-normalize, scale, convert to bf16
__global__ void normalize_kernel(const float* __restrict__ in,
                                 __nv_bfloat16* __restrict__ out, float scale) {
    int row = blockIdx.x * 8 + threadIdx.y;
    int lane = threadIdx.x;
    const float4* src = reinterpret_cast<const float4*>(in + (size_t)row * ND);
    float4 v0 = src[lane];
    float4 v1 = src[lane + 32];
    float ss = v0.x * v0.x + v0.y * v0.y + v0.z * v0.z + v0.w * v0.w
             + v1.x * v1.x + v1.y * v1.y + v1.z * v1.z + v1.w * v1.w;
#pragma unroll
    for (int o = 16; o > 0; o >>= 1) ss += __shfl_xor_sync(0xFFFFFFFFu, ss, o);
    float inv = scale / fmaxf(sqrtf(ss), 1e-12f);
    __nv_bfloat162* dst = reinterpret_cast<__nv_bfloat162*>(out + (size_t)row * ND);
    dst[lane * 2 + 0]  = __floats2bfloat162_rn(v0.x * inv, v0.y * inv);
    dst[lane * 2 + 1]  = __floats2bfloat162_rn(v0.z * inv, v0.w * inv);
    dst[lane * 2 + 64] = __floats2bfloat162_rn(v1.x * inv, v1.y * inv);
    dst[lane * 2 + 65] = __floats2bfloat162_rn(v1.z * inv, v1.w * inv);
}

// ---------------- persistent fused GEMM + exp2 + row/col sums ----------------
// CTA tile 128x128, K chunks of 64, 3-stage cp.async pipeline streaming
// continuously across tiles (no per-tile drain; epilogue overlaps next loads).
#define STAGE_BYTES 32768
#define SMEM_DYN (3 * STAGE_BYTES)

__global__ void __launch_bounds__(256, 2) gemm_lse_kernel() {
    extern __shared__ char smem[];
    uint32_t sbase = smem_u32(smem);
    int tid = threadIdx.x;
    int wid = tid >> 5, lid = tid & 31;
    int wr = wid & 3, wc = wid >> 2;   // warp tile: rows wr*32..+32, cols wc*64..+64
    int t0 = blockIdx.x;

    // ---- loader per-thread constants (strength-reduced SW128) ----
    int r0 = tid >> 3;
    int kbl = (tid & 7) * 16;
    uint32_t soff0 = (uint32_t)(r0 * 128 + (kbl ^ ((r0 & 7) << 4)));
    uint32_t ldoff = (uint32_t)(r0 * 512 + kbl);

    // load cursor: tile lt, chunk lc, stage ls
    int lt = t0, lc = 0, ls = 0;
    auto load_chunk = [&]() {
        const char* a = (const char*)g_qh + (size_t)(lt >> 7) * 65536 + ldoff + lc * 128;
        const char* b = (const char*)g_dh + (size_t)(lt & 127) * 65536 + ldoff + lc * 128;
        uint32_t sA = sbase + ls * STAGE_BYTES + soff0;
#pragma unroll
        for (int i = 0; i < 4; i++) {
            asm volatile("cp.async.cg.shared.global [%0], [%1], 16;"
                         :: "r"(sA + i * 4096), "l"(a + i * 16384));
            asm volatile("cp.async.cg.shared.global [%0], [%1], 16;"
                         :: "r"(sA + 16384 + i * 4096), "l"(b + i * 16384));
        }
        asm volatile("cp.async.commit_group;");
        if (++lc == 4) { lc = 0; lt += NCTA; }
        if (++ls == 3) ls = 0;
    };

    // ---- ldmatrix per-thread constants ----
    int fr = (lid & 7) + ((lid >> 3) & 1) * 8;
    uint32_t cswz = (uint32_t)((lid & 7) << 4);
    uint32_t hi16 = ((lid >> 4) & 1) * 16;
    uint32_t rbA[2], rbB[4];
#pragma unroll
    for (int mt = 0; mt < 2; mt++) rbA[mt] = (uint32_t)((wr * 32 + mt * 16 + fr) * 128);
#pragma unroll
    for (int np = 0; np < 4; np++) rbB[np] = (uint32_t)((wc * 64 + np * 16 + fr) * 128);

    float acc[2][8][4];
#pragma unroll
    for (int mt = 0; mt < 2; mt++)
#pragma unroll
        for (int nt = 0; nt < 8; nt++)
#pragma unroll
            for (int j = 0; j < 4; j++) acc[mt][nt][j] = 0.0f;

    int ntiles = (NB / 128) * (NB / 128);            // 16384
    int my_tiles = (ntiles - t0 + NCTA - 1) / NCTA;  // 55 or 56
    int G = my_tiles * 4;

    load_chunk();
    if (G > 1) load_chunk();

    int cs = 0;        // compute stage
    int ct = t0;       // compute tile (for epilogue)

    for (int g = 0; g < G; g++) {
        if (g < G - 1) { asm volatile("cp.async.wait_group 1;"); }
        else           { asm volatile("cp.async.wait_group 0;"); }
        __syncthreads();
        if (g + 2 < G) load_chunk();

        uint32_t aS = sbase + cs * STAGE_BYTES;
        uint32_t bS = aS + 16384;

#pragma unroll
        for (int ks = 0; ks < 4; ks++) {
            uint32_t kx = ((uint32_t)(ks * 32) + hi16) ^ cswz;
            uint32_t a[2][4], b[8][2];
#pragma unroll
            for (int mt = 0; mt < 2; mt++)
                asm volatile("ldmatrix.sync.aligned.m8n8.x4.shared.b16 {%0,%1,%2,%3}, [%4];"
                             : "=r"(a[mt][0]), "=r"(a[mt][1]), "=r"(a[mt][2]), "=r"(a[mt][3])
                             : "r"(aS + rbA[mt] + kx));
#pragma unroll
            for (int np = 0; np < 4; np++) {
                uint32_t r0_, r1_, r2_, r3_;
                asm volatile("ldmatrix.sync.aligned.m8n8.x4.shared.b16 {%0,%1,%2,%3}, [%4];"
                             : "=r"(r0_), "=r"(r1_), "=r"(r2_), "=r"(r3_)
                             : "r"(bS + rbB[np] + kx));
                b[2 * np][0] = r0_; b[2 * np + 1][0] = r1_;
                b[2 * np][1] = r2_; b[2 * np + 1][1] = r3_;
            }
#pragma unroll
            for (int mt = 0; mt < 2; mt++)
#pragma unroll
                for (int nt = 0; nt < 8; nt++)
                    asm volatile(
                        "mma.sync.aligned.m16n8k16.row.col.f32.bf16.bf16.f32 "
                        "{%0,%1,%2,%3}, {%4,%5,%6,%7}, {%8,%9}, {%0,%1,%2,%3};"
                        : "+f"(acc[mt][nt][0]), "+f"(acc[mt][nt][1]),
                          "+f"(acc[mt][nt][2]), "+f"(acc[mt][nt][3])
                        : "r"(a[mt][0]), "r"(a[mt][1]), "r"(a[mt][2]), "r"(a[mt][3]),
                          "r"(b[nt][0]), "r"(b[nt][1]));
        }
        if (++cs == 3) cs = 0;

        if ((g & 3) == 3) {
            // ---- epilogue for tile ct ----
            int bi = (ct >> 7) * 128, bj = (ct & 127) * 128;
            float rsum[2][2], csum[8][2];
#pragma unroll
            for (int mt = 0; mt < 2; mt++) { rsum[mt][0] = 0.0f; rsum[mt][1] = 0.0f; }
#pragma unroll
            for (int nt = 0; nt < 8; nt++) { csum[nt][0] = 0.0f; csum[nt][1] = 0.0f; }
#pragma unroll
            for (int mt = 0; mt < 2; mt++)
#pragma unroll
                for (int nt = 0; nt < 8; nt++) {
                    float e0 = ex2_approx(acc[mt][nt][0]);
                    float e1 = ex2_approx(acc[mt][nt][1]);
                    float e2 = ex2_approx(acc[mt][nt][2]);
                    float e3 = ex2_approx(acc[mt][nt][3]);
                    rsum[mt][0] += e0 + e1;
                    rsum[mt][1] += e2 + e3;
                    csum[nt][0] += e0 + e2;
                    csum[nt][1] += e1 + e3;
                }
#pragma unroll
            for (int mt = 0; mt < 2; mt++)
#pragma unroll
                for (int h = 0; h < 2; h++) {
                    float v = rsum[mt][h];
                    v += __shfl_xor_sync(0xFFFFFFFFu, v, 1);
                    v += __shfl_xor_sync(0xFFFFFFFFu, v, 2);
                    rsum[mt][h] = v;
                }
            if ((lid & 3) == 0) {
                int r = bi + wr * 32 + (lid >> 2);
                atomicAdd(&g_rowsum[r + 0],  rsum[0][0]);
                atomicAdd(&g_rowsum[r + 8],  rsum[0][1]);
                atomicAdd(&g_rowsum[r + 16], rsum[1][0]);
                atomicAdd(&g_rowsum[r + 24], rsum[1][1]);
            }
#pragma unroll
            for (int nt = 0; nt < 8; nt++)
#pragma unroll
                for (int j = 0; j < 2; j++) {
                    float v = csum[nt][j];
                    v += __shfl_xor_sync(0xFFFFFFFFu, v, 4);
                    v += __shfl_xor_sync(0xFFFFFFFFu, v, 8);
                    v += __shfl_xor_sync(0xFFFFFFFFu, v, 16);
                    csum[nt][j] = v;
                }
            if (lid < 4) {
                int cb = bj + wc * 64 + lid * 2;
#pragma unroll
                for (int nt = 0; nt < 8; nt++) {
                    atomicAdd(&g_colsum[cb + nt * 8 + 0], csum[nt][0]);
                    atomicAdd(&g_colsum[cb + nt * 8 + 1], csum[nt][1]);
                }
            }
            ct += NCTA;
#pragma unroll
            for (int mt = 0; mt < 2; mt++)
#pragma unroll
                for (int nt = 0; nt < 8; nt++)
#pragma unroll
                    for (int j = 0; j < 4; j++) acc[mt][nt][j] = 0.0f;
        }
    }
}

// ---------------- final: exact fp32 diagonal + logs + mean ----------------
__global__ void final_kernel(const float* __restrict__ q, const float* __restrict__ d,
                             float* __restrict__ out) {
    int row = blockIdx.x * 8 + threadIdx.y;
    int lane = threadIdx.x;
    const float4* qs = reinterpret_cast<const float4*>(q + (size_t)row * ND);
    const float4* ds = reinterpret_cast<const float4*>(d + (size_t)row * ND);
    float4 a0 = qs[lane], a1 = qs[lane + 32];
    float4 b0 = ds[lane], b1 = ds[lane + 32];
    float sq = a0.x * a0.x + a0.y * a0.y + a0.z * a0.z + a0.w * a0.w
             + a1.x * a1.x + a1.y * a1.y + a1.z * a1.z + a1.w * a1.w;
    float sd = b0.x * b0.x + b0.y * b0.y + b0.z * b0.z + b0.w * b0.w
             + b1.x * b1.x + b1.y * b1.y + b1.z * b1.z + b1.w * b1.w;
    float dot = a0.x * b0.x + a0.y * b0.y + a0.z * b0.z + a0.w * b0.w
              + a1.x * b1.x + a1.y * b1.y + a1.z * b1.z + a1.w * b1.w;
#pragma unroll
    for (int o = 16; o > 0; o >>= 1) {
        sq += __shfl_xor_sync(0xFFFFFFFFu, sq, o);
        sd += __shfl_xor_sync(0xFFFFFFFFu, sd, o);
        dot += __shfl_xor_sync(0xFFFFFFFFu, dot, o);
    }
    if (lane == 0) {
        float nq = fmaxf(sqrtf(sq), 1e-12f);
        float nd = fmaxf(sqrtf(sd), 1e-12f);
        float diag = dot / (nq * nd) * (1.0f / 0.07f);
        float term = 0.5f * (logf(g_rowsum[row]) + logf(g_colsum[row])) - diag;
        atomicAdd(out, term * (1.0f / NB));
    }
}

extern "C" void kernel_launch(void* const* d_in, const int* in_sizes, int n_in,
                              void* d_out, int out_size) {
    const float* q = (const float*)d_in[0];
    const float* db = (const float*)d_in[1];
    float* out = (float*)d_out;

    const float K = 1.4426950408889634f / 0.07f;  // log2(e)/T folded into Q

    __nv_bfloat16* qh; __nv_bfloat16* dh;
    cudaGetSymbolAddress((void**)&qh, g_qh);
    cudaGetSymbolAddress((void**)&dh, g_dh);

    static bool attr_set = false;
    if (!attr_set) {
        cudaFuncSetAttribute(gemm_lse_kernel, cudaFuncAttributeMaxDynamicSharedMemorySize, SMEM_DYN);
        attr_set = true;
    }

    zero_kernel<<<(NB + 255) / 256, 256>>>(out);

    dim3 nblk(NB / 8);
    dim3 nthr(32, 8);
    normalize_kernel<<<nblk, nthr>>>(q, qh, K);
    normalize_kernel<<<nblk, nthr>>>(db, dh, 1.0f);

    gemm_lse_kernel<<<NCTA, 256, SMEM_DYN>>>();

    final_kernel<<<nblk, nthr>>>(q, db, out);
}

// round 6
// speedup vs baseline: 1.0799x; 1.0799x over previous
#include <cuda_runtime.h>
#include <cuda_bf16.h>
#include <cstdint>
#include <math.h>

#define NB 16384
#define ND 256
#define NCTA 296            // persistent CTAs: 2 per SM on 148 SMs

static __device__ __nv_bfloat16 g_qh[NB * ND];  // normalized Q * log2(e)/T, bf16
static __device__ __nv_bfloat16 g_dh[NB * ND];  // normalized D, bf16
static __device__ float g_rowsum[NB];
static __device__ float g_colsum[NB];

__device__ __forceinline__ uint32_t smem_u32(const void* p) {
    uint32_t a;
    asm("{ .reg .u64 t; cvta.to.shared.u64 t, %1; cvt.u32.u64 %0, t; }" : "=r"(a) : "l"(p));
    return a;
}
__device__ __forceinline__ float ex2_approx(float x) {
    float r; asm("ex2.approx.f32 %0, %1;" : "=f"(r) : "f"(x)); return r;
}

// ---------------- setup kernels ----------------
__global__ void zero_kernel(float* out) {
    int i = blockIdx.x * blockDim.x + threadIdx.x;
    if (i < NB) { g_rowsum[i] = 0.0f; g_colsum[i] = 0.0f; }
    if (i == 0) out[0] = 0.0f;
}

__global__ void normalize_kernel(const float* __restrict__ in,
                                 __nv_bfloat16* __restrict__ out, float scale) {
    int row = blockIdx.x * 8 + threadIdx.y;
    int lane = threadIdx.x;
    const float4* src = reinterpret_cast<const float4*>(in + (size_t)row * ND);
    float4 v0 = src[lane];
    float4 v1 = src[lane + 32];
    float ss = v0.x * v0.x + v0.y * v0.y + v0.z * v0.z + v0.w * v0.w
             + v1.x * v1.x + v1.y * v1.y + v1.z * v1.z + v1.w * v1.w;
#pragma unroll
    for (int o = 16; o > 0; o >>= 1) ss += __shfl_xor_sync(0xFFFFFFFFu, ss, o);
    float inv = scale / fmaxf(sqrtf(ss), 1e-12f);
    __nv_bfloat162* dst = reinterpret_cast<__nv_bfloat162*>(out + (size_t)row * ND);
    dst[lane * 2 + 0]  = __floats2bfloat162_rn(v0.x * inv, v0.y * inv);
    dst[lane * 2 + 1]  = __floats2bfloat162_rn(v0.z * inv, v0.w * inv);
    dst[lane * 2 + 64] = __floats2bfloat162_rn(v1.x * inv, v1.y * inv);
    dst[lane * 2 + 65] = __floats2bfloat162_rn(v1.z * inv, v1.w * inv);
}

// ---------------- persistent fused GEMM + exp2 + row/col sums ----------------
// CTA tile 128x128, K chunks of 64, 3-stage cp.async pipeline, STATIC stages
// via 3-tile (12-chunk) unrolled superblocks.
#define STAGE_BYTES 32768
#define SMEM_DYN (3 * STAGE_BYTES)
#define S0 0
#define S1 STAGE_BYTES
#define S2 (2 * STAGE_BYTES)

__global__ void __launch_bounds__(256, 2) gemm_lse_kernel() {
    extern __shared__ char smem[];
    uint32_t sbase = smem_u32(smem);
    int tid = threadIdx.x;
    int wid = tid >> 5, lid = tid & 31;
    int wr = wid & 3, wc = wid >> 2;   // warp tile: rows wr*32..+32, cols wc*64..+64
    int t0 = blockIdx.x;

    // ---- loader per-thread constants (strength-reduced SW128) ----
    int r0 = tid >> 3;
    int kbl = (tid & 7) * 16;
    uint32_t soff0 = (uint32_t)(r0 * 128 + (kbl ^ ((r0 & 7) << 4)));
    uint32_t ldoff = (uint32_t)(r0 * 512 + kbl);
    const char* Qbase = (const char*)g_qh;
    const char* Dbase = (const char*)g_dh;

    // cursors (all 32-bit)
    uint32_t lt = (uint32_t)t0;  // load tile
    uint32_t lc = 0;             // load chunk in tile
    int ct = t0;                 // epilogue tile
    int my_tiles = (16384 - t0 + NCTA - 1) / NCTA;
    int G = my_tiles * 4;
    int g = 0;                   // compute chunk counter

    // ---- ldmatrix per-thread constants ----
    int fr = (lid & 7) + ((lid >> 3) & 1) * 8;
    uint32_t cswz = (uint32_t)((lid & 7) << 4);
    uint32_t hi16 = ((lid >> 4) & 1) * 16;
    uint32_t rbA[2], rbB[4];
#pragma unroll
    for (int mt = 0; mt < 2; mt++) rbA[mt] = (uint32_t)((wr * 32 + mt * 16 + fr) * 128);
#pragma unroll
    for (int np = 0; np < 4; np++) rbB[np] = (uint32_t)((wc * 64 + np * 16 + fr) * 128);

    float acc[2][8][4];
#pragma unroll
    for (int mt = 0; mt < 2; mt++)
#pragma unroll
        for (int nt = 0; nt < 8; nt++)
#pragma unroll
            for (int j = 0; j < 4; j++) acc[mt][nt][j] = 0.0f;

#define LOAD_CHUNK(SOFF) do {                                                     \
    uint32_t aoff = ((lt >> 7) << 16) + ldoff + (lc << 7);                        \
    uint32_t boff = ((lt & 127u) << 16) + ldoff + (lc << 7);                      \
    const char* a_ = Qbase + aoff;                                                \
    const char* b_ = Dbase + boff;                                                \
    uint32_t sA_ = sbase + (SOFF) + soff0;                                        \
    _Pragma("unroll")                                                             \
    for (int i_ = 0; i_ < 4; i_++) {                                              \
        asm volatile("cp.async.cg.shared.global [%0], [%1], 16;"                  \
                     :: "r"(sA_ + i_ * 4096), "l"(a_ + i_ * 16384));              \
        asm volatile("cp.async.cg.shared.global [%0], [%1], 16;"                  \
                     :: "r"(sA_ + 16384 + i_ * 4096), "l"(b_ + i_ * 16384));      \
    }                                                                             \
    asm volatile("cp.async.commit_group;");                                       \
    if (++lc == 4) { lc = 0; lt += NCTA; }                                        \
} while (0)

#define COMPUTE_CHUNK(SOFF) do {                                                  \
    uint32_t aS = sbase + (SOFF);                                                 \
    uint32_t bS = aS + 16384;                                                     \
    _Pragma("unroll")                                                             \
    for (int ks = 0; ks < 4; ks++) {                                              \
        uint32_t kx = ((uint32_t)(ks * 32) + hi16) ^ cswz;                        \
        uint32_t a[2][4], b[8][2];                                                \
        _Pragma("unroll")                                                         \
        for (int mt = 0; mt < 2; mt++)                                            \
            asm volatile("ldmatrix.sync.aligned.m8n8.x4.shared.b16 {%0,%1,%2,%3}, [%4];" \
                         : "=r"(a[mt][0]), "=r"(a[mt][1]), "=r"(a[mt][2]), "=r"(a[mt][3]) \
                         : "r"(aS + rbA[mt] + kx));                               \
        _Pragma("unroll")                                                         \
        for (int np = 0; np < 4; np++) {                                          \
            uint32_t q0_, q1_, q2_, q3_;                                          \
            asm volatile("ldmatrix.sync.aligned.m8n8.x4.shared.b16 {%0,%1,%2,%3}, [%4];" \
                         : "=r"(q0_), "=r"(q1_), "=r"(q2_), "=r"(q3_)             \
                         : "r"(bS + rbB[np] + kx));                               \
            b[2 * np][0] = q0_; b[2 * np + 1][0] = q1_;                           \
            b[2 * np][1] = q2_; b[2 * np + 1][1] = q3_;                           \
        }                                                                         \
        _Pragma("unroll")                                                         \
        for (int mt = 0; mt < 2; mt++)                                            \
            _Pragma("unroll")                                                     \
            for (int nt = 0; nt < 8; nt++)                                        \
                asm volatile(                                                     \
                    "mma.sync.aligned.m16n8k16.row.col.f32.bf16.bf16.f32 "        \
                    "{%0,%1,%2,%3}, {%4,%5,%6,%7}, {%8,%9}, {%0,%1,%2,%3};"       \
                    : "+f"(acc[mt][nt][0]), "+f"(acc[mt][nt][1]),                 \
                      "+f"(acc[mt][nt][2]), "+f"(acc[mt][nt][3])                  \
                    : "r"(a[mt][0]), "r"(a[mt][1]), "r"(a[mt][2]), "r"(a[mt][3]), \
                      "r"(b[nt][0]), "r"(b[nt][1]));                              \
    }                                                                             \
} while (0)

#define EPILOGUE() do {                                                           \
    int bi = (ct >> 7) * 128, bj = (ct & 127) * 128;                              \
    float rsum[2][2], csum[8][2];                                                 \
    _Pragma("unroll")                                                             \
    for (int mt = 0; mt < 2; mt++) { rsum[mt][0] = 0.0f; rsum[mt][1] = 0.0f; }    \
    _Pragma("unroll")                                                             \
    for (int nt = 0; nt < 8; nt++) { csum[nt][0] = 0.0f; csum[nt][1] = 0.0f; }    \
    _Pragma("unroll")                                                             \
    for (int mt = 0; mt < 2; mt++)                                                \
        _Pragma("unroll")                                                         \
        for (int nt = 0; nt < 8; nt++) {                                          \
            float e0 = ex2_approx(acc[mt][nt][0]);                                \
            float e1 = ex2_approx(acc[mt][nt][1]);                                \
            float e2 = ex2_approx(acc[mt][nt][2]);                                \
            float e3 = ex2_approx(acc[mt][nt][3]);                                \
            rsum[mt][0] += e0 + e1; rsum[mt][1] += e2 + e3;                       \
            csum[nt][0] += e0 + e2; csum[nt][1] += e1 + e3;                       \
            acc[mt][nt][0] = 0.0f; acc[mt][nt][1] = 0.0f;                         \
            acc[mt][nt][2] = 0.0f; acc[mt][nt][3] = 0.0f;                         \
        }                                                                         \
    _Pragma("unroll")                                                             \
    for (int mt = 0; mt < 2; mt++)                                                \
        _Pragma("unroll")                                                         \
        for (int h = 0; h < 2; h++) {                                             \
            float v = rsum[mt][h];                                                \
            v += __shfl_xor_sync(0xFFFFFFFFu, v, 1);                              \
            v += __shfl_xor_sync(0xFFFFFFFFu, v, 2);                              \
            rsum[mt][h] = v;                                                      \
        }                                                                         \
    if ((lid & 3) == 0) {                                                         \
        int r_ = bi + wr * 32 + (lid >> 2);                                       \
        atomicAdd(&g_rowsum[r_ + 0],  rsum[0][0]);                                \
        atomicAdd(&g_rowsum[r_ + 8],  rsum[0][1]);                                \
        atomicAdd(&g_rowsum[r_ + 16], rsum[1][0]);                                \
        atomicAdd(&g_rowsum[r_ + 24], rsum[1][1]);                                \
    }                                                                             \
    _Pragma("unroll")                                                             \
    for (int nt = 0; nt < 8; nt++)                                                \
        _Pragma("unroll")                                                         \
        for (int j = 0; j < 2; j++) {                                             \
            float v = csum[nt][j];                                                \
            v += __shfl_xor_sync(0xFFFFFFFFu, v, 4);                              \
            v += __shfl_xor_sync(0xFFFFFFFFu, v, 8);                              \
            v += __shfl_xor_sync(0xFFFFFFFFu, v, 16);                             \
            csum[nt][j] = v;                                                      \
        }                                                                         \
    if (lid < 4) {                                                                \
        int cb = bj + wc * 64 + lid * 2;                                          \
        _Pragma("unroll")                                                         \
        for (int nt = 0; nt < 8; nt++) {                                          \
            atomicAdd(&g_colsum[cb + nt * 8 + 0], csum[nt][0]);                   \
            atomicAdd(&g_colsum[cb + nt * 8 + 1], csum[nt][1]);                   \
        }                                                                         \
    }                                                                             \
    ct += NCTA;                                                                   \
} while (0)

#define CHUNK_STEP(CSOFF, LSOFF, DO_EPI) do {                                     \
    if (g == G - 1) { asm volatile("cp.async.wait_group 0;"); }                   \
    else            { asm volatile("cp.async.wait_group 1;"); }                   \
    __syncthreads();                                                              \
    if (g + 2 < G) { LOAD_CHUNK(LSOFF); }                                         \
    COMPUTE_CHUNK(CSOFF);                                                         \
    g++;                                                                          \
    if (DO_EPI) { EPILOGUE(); }                                                   \
} while (0)

    // prologue: 2 chunks in flight
    LOAD_CHUNK(S0);
    LOAD_CHUNK(S1);

    int nsuper = my_tiles / 3;
    int rem = my_tiles - nsuper * 3;
    for (int sb = 0; sb < nsuper; sb++) {
        CHUNK_STEP(S0, S2, 0);
        CHUNK_STEP(S1, S0, 0);
        CHUNK_STEP(S2, S1, 0);
        CHUNK_STEP(S0, S2, 1);
        CHUNK_STEP(S1, S0, 0);
        CHUNK_STEP(S2, S1, 0);
        CHUNK_STEP(S0, S2, 0);
        CHUNK_STEP(S1, S0, 1);
        CHUNK_STEP(S2, S1, 0);
        CHUNK_STEP(S0, S2, 0);
        CHUNK_STEP(S1, S0, 0);
        CHUNK_STEP(S2, S1, 1);
    }
    if (rem >= 1) {
        CHUNK_STEP(S0, S2, 0);
        CHUNK_STEP(S1, S0, 0);
        CHUNK_STEP(S2, S1, 0);
        CHUNK_STEP(S0, S2, 1);
    }
    if (rem == 2) {
        CHUNK_STEP(S1, S0, 0);
        CHUNK_STEP(S2, S1, 0);
        CHUNK_STEP(S0, S2, 0);
        CHUNK_STEP(S1, S0, 1);
    }
}

// ---------------- final: exact fp32 diagonal + logs + mean ----------------
__global__ void final_kernel(const float* __restrict__ q, const float* __restrict__ d,
                             float* __restrict__ out) {
    int row = blockIdx.x * 8 + threadIdx.y;
    int lane = threadIdx.x;
    const float4* qs = reinterpret_cast<const float4*>(q + (size_t)row * ND);
    const float4* ds = reinterpret_cast<const float4*>(d + (size_t)row * ND);
    float4 a0 = qs[lane], a1 = qs[lane + 32];
    float4 b0 = ds[lane], b1 = ds[lane + 32];
    float sq = a0.x * a0.x + a0.y * a0.y + a0.z * a0.z + a0.w * a0.w
             + a1.x * a1.x + a1.y * a1.y + a1.z * a1.z + a1.w * a1.w;
    float sd = b0.x * b0.x + b0.y * b0.y + b0.z * b0.z + b0.w * b0.w
             + b1.x * b1.x + b1.y * b1.y + b1.z * b1.z + b1.w * b1.w;
    float dot = a0.x * b0.x + a0.y * b0.y + a0.z * b0.z + a0.w * b0.w
              + a1.x * b1.x + a1.y * b1.y + a1.z * b1.z + a1.w * b1.w;
#pragma unroll
    for (int o = 16; o > 0; o >>= 1) {
        sq += __shfl_xor_sync(0xFFFFFFFFu, sq, o);
        sd += __shfl_xor_sync(0xFFFFFFFFu, sd, o);
        dot += __shfl_xor_sync(0xFFFFFFFFu, dot, o);
    }
    if (lane == 0) {
        float nq = fmaxf(sqrtf(sq), 1e-12f);
        float nd = fmaxf(sqrtf(sd), 1e-12f);
        float diag = dot / (nq * nd) * (1.0f / 0.07f);
        float term = 0.5f * (logf(g_rowsum[row]) + logf(g_colsum[row])) - diag;
        atomicAdd(out, term * (1.0f / NB));
    }
}

extern "C" void kernel_launch(void* const* d_in, const int* in_sizes, int n_in,
                              void* d_out, int out_size) {
    const float* q = (const float*)d_in[0];
    const float* db = (const float*)d_in[1];
    float* out = (float*)d_out;

    const float K = 1.4426950408889634f / 0.07f;  // log2(e)/T folded into Q

    __nv_bfloat16* qh; __nv_bfloat16* dh;
    cudaGetSymbolAddress((void**)&qh, g_qh);
    cudaGetSymbolAddress((void**)&dh, g_dh);

    static bool attr_set = false;
    if (!attr_set) {
        cudaFuncSetAttribute(gemm_lse_kernel, cudaFuncAttributeMaxDynamicSharedMemorySize, SMEM_DYN);
        attr_set = true;
    }

    zero_kernel<<<(NB + 255) / 256, 256>>>(out);

    dim3 nblk(NB / 8);
    dim3 nthr(32, 8);
    normalize_kernel<<<nblk, nthr>>>(q, qh, K);
    normalize_kernel<<<nblk, nthr>>>(db, dh, 1.0f);

    gemm_lse_kernel<<<NCTA, 256, SMEM_DYN>>>();

    final_kernel<<<nblk, nthr>>>(q, db, out);
}

// round 7
// speedup vs baseline: 1.1911x; 1.1030x over previous
#include <cuda_runtime.h>
#include <cuda_bf16.h>
#include <cstdint>
#include <math.h>

#define NB 16384
#define ND 256

static __device__ __nv_bfloat16 g_qh[NB * ND];  // normalized Q * log2(e)/T, bf16
static __device__ __nv_bfloat16 g_dh[NB * ND];  // normalized D, bf16
static __device__ float g_rowsum[NB];
static __device__ float g_colsum[NB];

__device__ __forceinline__ uint32_t smem_u32(const void* p) {
    uint32_t a;
    asm("{ .reg .u64 t; cvta.to.shared.u64 t, %1; cvt.u32.u64 %0, t; }" : "=r"(a) : "l"(p));
    return a;
}
__device__ __forceinline__ float ex2_approx(float x) {
    float r; asm("ex2.approx.f32 %0, %1;" : "=f"(r) : "f"(x)); return r;
}

// ---------------- setup kernels ----------------
__global__ void zero_kernel(float* out) {
    int i = blockIdx.x * blockDim.x + threadIdx.x;
    if (i < NB) { g_rowsum[i] = 0.0f; g_colsum[i] = 0.0f; }
    if (i == 0) out[0] = 0.0f;
}

__global__ void normalize_kernel(const float* __restrict__ in,
                                 __nv_bfloat16* __restrict__ out, float scale) {
    int row = blockIdx.x * 8 + threadIdx.y;
    int lane = threadIdx.x;
    const float4* src = reinterpret_cast<const float4*>(in + (size_t)row * ND);
    float4 v0 = src[lane];
    float4 v1 = src[lane + 32];
    float ss = v0.x * v0.x + v0.y * v0.y + v0.z * v0.z + v0.w * v0.w
             + v1.x * v1.x + v1.y * v1.y + v1.z * v1.z + v1.w * v1.w;
#pragma unroll
    for (int o = 16; o > 0; o >>= 1) ss += __shfl_xor_sync(0xFFFFFFFFu, ss, o);
    float inv = scale / fmaxf(sqrtf(ss), 1e-12f);
    __nv_bfloat162* dst = reinterpret_cast<__nv_bfloat162*>(out + (size_t)row * ND);
    dst[lane * 2 + 0]  = __floats2bfloat162_rn(v0.x * inv, v0.y * inv);
    dst[lane * 2 + 1]  = __floats2bfloat162_rn(v0.z * inv, v0.w * inv);
    dst[lane * 2 + 64] = __floats2bfloat162_rn(v1.x * inv, v1.y * inv);
    dst[lane * 2 + 65] = __floats2bfloat162_rn(v1.z * inv, v1.w * inv);
}

// ---------------- fused mma.sync GEMM + exp2 + row/col sums ----------------
// CTA tile 128x128, K chunks of 64, 3-stage cp.async pipeline (R4 structure),
// last chunk interleaves exp2/col-reduction with the MMA stream.
#define STAGE_BYTES 32768
#define SMEM_DYN (3 * STAGE_BYTES)

__global__ void __launch_bounds__(256, 2) gemm_lse_kernel() {
    extern __shared__ char smem[];
    uint32_t sbase = smem_u32(smem);
    int tid = threadIdx.x;
    int wid = tid >> 5, lid = tid & 31;
    int wr = wid & 3, wc = wid >> 2;   // warp tile: rows wr*32..+32, cols wc*64..+64
    int bi = blockIdx.y * 128, bj = blockIdx.x * 128;

    // ---- loader per-thread constants (strength-reduced SW128) ----
    int r0 = tid >> 3;
    int kbl = (tid & 7) * 16;
    uint32_t soff0 = (uint32_t)(r0 * 128 + (kbl ^ ((r0 & 7) << 4)));
    const char* Ag = (const char*)(g_qh + (size_t)bi * ND) + r0 * 512 + kbl;
    const char* Bg = (const char*)(g_dh + (size_t)bj * ND) + r0 * 512 + kbl;

    auto load_chunk = [&](int c, int s) {
        uint32_t sA = sbase + s * STAGE_BYTES + soff0;
        const char* a = Ag + c * 128;
        const char* b = Bg + c * 128;
#pragma unroll
        for (int i = 0; i < 4; i++) {
            asm volatile("cp.async.cg.shared.global [%0], [%1], 16;"
                         :: "r"(sA + i * 4096), "l"(a + i * 16384));
            asm volatile("cp.async.cg.shared.global [%0], [%1], 16;"
                         :: "r"(sA + 16384 + i * 4096), "l"(b + i * 16384));
        }
        asm volatile("cp.async.commit_group;");
    };

    float acc[2][8][4];
#pragma unroll
    for (int mt = 0; mt < 2; mt++)
#pragma unroll
        for (int nt = 0; nt < 8; nt++)
#pragma unroll
            for (int j = 0; j < 4; j++) acc[mt][nt][j] = 0.0f;

    // ---- ldmatrix per-thread constants ----
    int fr = (lid & 7) + ((lid >> 3) & 1) * 8;
    uint32_t cswz = (uint32_t)((lid & 7) << 4);
    uint32_t hi16 = ((lid >> 4) & 1) * 16;
    uint32_t rbA[2], rbB[4];
#pragma unroll
    for (int mt = 0; mt < 2; mt++) rbA[mt] = (uint32_t)((wr * 32 + mt * 16 + fr) * 128);
#pragma unroll
    for (int np = 0; np < 4; np++) rbB[np] = (uint32_t)((wc * 64 + np * 16 + fr) * 128);

    // ---- prologue: fill 3 stages ----
    load_chunk(0, 0);
    load_chunk(1, 1);
    load_chunk(2, 2);

    // ---- chunks 0..2: standard compute ----
#pragma unroll
    for (int c = 0; c < 3; c++) {
        if (c == 0) { asm volatile("cp.async.wait_group 2;"); }
        else        { asm volatile("cp.async.wait_group 1;"); }
        __syncthreads();
        if (c == 1) load_chunk(3, 0);   // stage 0 consumed after c=0

        uint32_t aS = sbase + c * STAGE_BYTES;
        uint32_t bS = aS + 16384;
#pragma unroll
        for (int ks = 0; ks < 4; ks++) {
            uint32_t kx = ((uint32_t)(ks * 32) + hi16) ^ cswz;
            uint32_t a[2][4], b[8][2];
#pragma unroll
            for (int mt = 0; mt < 2; mt++)
                asm volatile("ldmatrix.sync.aligned.m8n8.x4.shared.b16 {%0,%1,%2,%3}, [%4];"
                             : "=r"(a[mt][0]), "=r"(a[mt][1]), "=r"(a[mt][2]), "=r"(a[mt][3])
                             : "r"(aS + rbA[mt] + kx));
#pragma unroll
            for (int np = 0; np < 4; np++) {
                uint32_t q0, q1, q2, q3;
                asm volatile("ldmatrix.sync.aligned.m8n8.x4.shared.b16 {%0,%1,%2,%3}, [%4];"
                             : "=r"(q0), "=r"(q1), "=r"(q2), "=r"(q3)
                             : "r"(bS + rbB[np] + kx));
                b[2 * np][0] = q0; b[2 * np + 1][0] = q1;
                b[2 * np][1] = q2; b[2 * np + 1][1] = q3;
            }
#pragma unroll
            for (int mt = 0; mt < 2; mt++)
#pragma unroll
                for (int nt = 0; nt < 8; nt++)
                    asm volatile(
                        "mma.sync.aligned.m16n8k16.row.col.f32.bf16.bf16.f32 "
                        "{%0,%1,%2,%3}, {%4,%5,%6,%7}, {%8,%9}, {%0,%1,%2,%3};"
                        : "+f"(acc[mt][nt][0]), "+f"(acc[mt][nt][1]),
                          "+f"(acc[mt][nt][2]), "+f"(acc[mt][nt][3])
                        : "r"(a[mt][0]), "r"(a[mt][1]), "r"(a[mt][2]), "r"(a[mt][3]),
                          "r"(b[nt][0]), "r"(b[nt][1]));
        }
        __syncthreads();
    }

    // ---- chunk 3: interleaved compute + epilogue ----
    asm volatile("cp.async.wait_group 0;");
    __syncthreads();
    {
        uint32_t aS = sbase;             // stage 0
        uint32_t bS = aS + 16384;

        // preload all A fragments for this chunk (8 LDSM, 32 regs)
        uint32_t af[4][2][4];
#pragma unroll
        for (int ks = 0; ks < 4; ks++) {
            uint32_t kx = ((uint32_t)(ks * 32) + hi16) ^ cswz;
#pragma unroll
            for (int mt = 0; mt < 2; mt++)
                asm volatile("ldmatrix.sync.aligned.m8n8.x4.shared.b16 {%0,%1,%2,%3}, [%4];"
                             : "=r"(af[ks][mt][0]), "=r"(af[ks][mt][1]),
                               "=r"(af[ks][mt][2]), "=r"(af[ks][mt][3])
                             : "r"(aS + rbA[mt] + kx));
        }

        float rsum[2][2];
        rsum[0][0] = 0.0f; rsum[0][1] = 0.0f; rsum[1][0] = 0.0f; rsum[1][1] = 0.0f;

#pragma unroll
        for (int np = 0; np < 4; np++) {
            // finish both columns of this pair across all 4 k-steps
#pragma unroll
            for (int ks = 0; ks < 4; ks++) {
                uint32_t kx = ((uint32_t)(ks * 32) + hi16) ^ cswz;
                uint32_t q0, q1, q2, q3;
                asm volatile("ldmatrix.sync.aligned.m8n8.x4.shared.b16 {%0,%1,%2,%3}, [%4];"
                             : "=r"(q0), "=r"(q1), "=r"(q2), "=r"(q3)
                             : "r"(bS + rbB[np] + kx));
#pragma unroll
                for (int mt = 0; mt < 2; mt++) {
                    asm volatile(
                        "mma.sync.aligned.m16n8k16.row.col.f32.bf16.bf16.f32 "
                        "{%0,%1,%2,%3}, {%4,%5,%6,%7}, {%8,%9}, {%0,%1,%2,%3};"
                        : "+f"(acc[mt][2 * np][0]), "+f"(acc[mt][2 * np][1]),
                          "+f"(acc[mt][2 * np][2]), "+f"(acc[mt][2 * np][3])
                        : "r"(af[ks][mt][0]), "r"(af[ks][mt][1]),
                          "r"(af[ks][mt][2]), "r"(af[ks][mt][3]),
                          "r"(q0), "r"(q2));
                    asm volatile(
                        "mma.sync.aligned.m16n8k16.row.col.f32.bf16.bf16.f32 "
                        "{%0,%1,%2,%3}, {%4,%5,%6,%7}, {%8,%9}, {%0,%1,%2,%3};"
                        : "+f"(acc[mt][2 * np + 1][0]), "+f"(acc[mt][2 * np + 1][1]),
                          "+f"(acc[mt][2 * np + 1][2]), "+f"(acc[mt][2 * np + 1][3])
                        : "r"(af[ks][mt][0]), "r"(af[ks][mt][1]),
                          "r"(af[ks][mt][2]), "r"(af[ks][mt][3]),
                          "r"(q1), "r"(q3));
                }
            }
            // these two columns are final: exp2 + partial sums now (overlaps
            // the next pair's MMAs via warp drift / ILP)
            float csum[2][2];
            csum[0][0] = 0.0f; csum[0][1] = 0.0f; csum[1][0] = 0.0f; csum[1][1] = 0.0f;
#pragma unroll
            for (int mt = 0; mt < 2; mt++)
#pragma unroll
                for (int p = 0; p < 2; p++) {
                    int nt = 2 * np + p;
                    float e0 = ex2_approx(acc[mt][nt][0]);
                    float e1 = ex2_approx(acc[mt][nt][1]);
                    float e2 = ex2_approx(acc[mt][nt][2]);
                    float e3 = ex2_approx(acc[mt][nt][3]);
                    rsum[mt][0] += e0 + e1;
                    rsum[mt][1] += e2 + e3;
                    csum[p][0] += e0 + e2;
                    csum[p][1] += e1 + e3;
                }
#pragma unroll
            for (int p = 0; p < 2; p++)
#pragma unroll
                for (int j = 0; j < 2; j++) {
                    float v = csum[p][j];
                    v += __shfl_xor_sync(0xFFFFFFFFu, v, 4);
                    v += __shfl_xor_sync(0xFFFFFFFFu, v, 8);
                    v += __shfl_xor_sync(0xFFFFFFFFu, v, 16);
                    csum[p][j] = v;
                }
            if (lid < 4) {
                int cb = bj + wc * 64 + np * 16 + lid * 2;
                atomicAdd(&g_colsum[cb + 0], csum[0][0]);
                atomicAdd(&g_colsum[cb + 1], csum[0][1]);
                atomicAdd(&g_colsum[cb + 8], csum[1][0]);
                atomicAdd(&g_colsum[cb + 9], csum[1][1]);
            }
        }

        // rows: reduce across the lane quad
#pragma unroll
        for (int mt = 0; mt < 2; mt++)
#pragma unroll
            for (int h = 0; h < 2; h++) {
                float v = rsum[mt][h];
                v += __shfl_xor_sync(0xFFFFFFFFu, v, 1);
                v += __shfl_xor_sync(0xFFFFFFFFu, v, 2);
                rsum[mt][h] = v;
            }
        if ((lid & 3) == 0) {
            int r = bi + wr * 32 + (lid >> 2);
            atomicAdd(&g_rowsum[r + 0],  rsum[0][0]);
            atomicAdd(&g_rowsum[r + 8],  rsum[0][1]);
            atomicAdd(&g_rowsum[r + 16], rsum[1][0]);
            atomicAdd(&g_rowsum[r + 24], rsum[1][1]);
        }
    }
}

// ---------------- final: exact fp32 diagonal + logs + mean ----------------
__global__ void final_kernel(const float* __restrict__ q, const float* __restrict__ d,
                             float* __restrict__ out) {
    int row = blockIdx.x * 8 + threadIdx.y;
    int lane = threadIdx.x;
    const float4* qs = reinterpret_cast<const float4*>(q + (size_t)row * ND);
    const float4* ds = reinterpret_cast<const float4*>(d + (size_t)row * ND);
    float4 a0 = qs[lane], a1 = qs[lane + 32];
    float4 b0 = ds[lane], b1 = ds[lane + 32];
    float sq = a0.x * a0.x + a0.y * a0.y + a0.z * a0.z + a0.w * a0.w
             + a1.x * a1.x + a1.y * a1.y + a1.z * a1.z + a1.w * a1.w;
    float sd = b0.x * b0.x + b0.y * b0.y + b0.z * b0.z + b0.w * b0.w
             + b1.x * b1.x + b1.y * b1.y + b1.z * b1.z + b1.w * b1.w;
    float dot = a0.x * b0.x + a0.y * b0.y + a0.z * b0.z + a0.w * b0.w
              + a1.x * b1.x + a1.y * b1.y + a1.z * b1.z + a1.w * b1.w;
#pragma unroll
    for (int o = 16; o > 0; o >>= 1) {
        sq += __shfl_xor_sync(0xFFFFFFFFu, sq, o);
        sd += __shfl_xor_sync(0xFFFFFFFFu, sd, o);
        dot += __shfl_xor_sync(0xFFFFFFFFu, dot, o);
    }
    if (lane == 0) {
        float nq = fmaxf(sqrtf(sq), 1e-12f);
        float nd = fmaxf(sqrtf(sd), 1e-12f);
        float diag = dot / (nq * nd) * (1.0f / 0.07f);
        float term = 0.5f * (logf(g_rowsum[row]) + logf(g_colsum[row])) - diag;
        atomicAdd(out, term * (1.0f / NB));
    }
}

extern "C" void kernel_launch(void* const* d_in, const int* in_sizes, int n_in,
                              void* d_out, int out_size) {
    const float* q = (const float*)d_in[0];
    const float* db = (const float*)d_in[1];
    float* out = (float*)d_out;

    const float K = 1.4426950408889634f / 0.07f;  // log2(e)/T folded into Q

    __nv_bfloat16* qh; __nv_bfloat16* dh;
    cudaGetSymbolAddress((void**)&qh, g_qh);
    cudaGetSymbolAddress((void**)&dh, g_dh);

    static bool attr_set = false;
    if (!attr_set) {
        cudaFuncSetAttribute(gemm_lse_kernel, cudaFuncAttributeMaxDynamicSharedMemorySize, SMEM_DYN);
        attr_set = true;
    }

    zero_kernel<<<(NB + 255) / 256, 256>>>(out);

    dim3 nblk(NB / 8);
    dim3 nthr(32, 8);
    normalize_kernel<<<nblk, nthr>>>(q, qh, K);
    normalize_kernel<<<nblk, nthr>>>(db, dh, 1.0f);

    dim3 ggrid(NB / 128, NB / 128);
    gemm_lse_kernel<<<ggrid, 256, SMEM_DYN>>>();

    final_kernel<<<nblk, nthr>>>(q, db, out);
}